// round 2
// baseline (speedup 1.0000x reference)
#include <cuda_runtime.h>
#include <cstdint>
#include <math.h>

#define NN 100000
#define NG 100
#define NE 1000000
#define HD 256
#define NT 4

__device__ float g_h[(size_t)NN * HD];
__device__ float g_trans[(size_t)NN * NT * HD];
__device__ float g_msgs[(size_t)NN * HD];
__device__ float g_gx[(size_t)NN * 3 * HD];
__device__ float g_gh[(size_t)NN * 3 * HD];
__device__ float g_gate[NN];
__device__ float g_outs[2 * NN];
__device__ float g_sums[NG];
__device__ unsigned g_gmax;
__device__ int g_deg[NN];
__device__ int g_rowoff[NN + 1];
__device__ int g_cursor[NN];
__device__ int g_csr[NE];
__device__ int g_cum[NG];

__device__ __forceinline__ float to_tf32(float x) {
  unsigned u;
  asm("cvt.rna.tf32.f32 %0, %1;" : "=r"(u) : "f"(x));
  return __uint_as_float(u);
}
__device__ __forceinline__ void mma_tf32(float* d, const unsigned* a, const unsigned* b) {
  asm volatile(
      "mma.sync.aligned.m16n8k8.row.col.f32.tf32.tf32.f32 "
      "{%0,%1,%2,%3}, {%4,%5,%6,%7}, {%8,%9}, {%0,%1,%2,%3};\n"
      : "+f"(d[0]), "+f"(d[1]), "+f"(d[2]), "+f"(d[3])
      : "r"(a[0]), "r"(a[1]), "r"(a[2]), "r"(a[3]), "r"(b[0]), "r"(b[1]));
}
__device__ __forceinline__ unsigned fenc(float f) {
  unsigned u = __float_as_uint(f);
  return (u & 0x80000000u) ? ~u : (u | 0x80000000u);
}
__device__ __forceinline__ float fdec(unsigned e) {
  return (e & 0x80000000u) ? __uint_as_float(e & 0x7fffffffu) : __uint_as_float(~e);
}
__device__ __forceinline__ int find_seg(int v) {
  int lo = 0, hi = NG;
  while (lo < hi) { int mid = (lo + hi) >> 1; if (g_cum[mid] > v) hi = mid; else lo = mid + 1; }
  return lo;
}
__device__ __forceinline__ float gru1(float xz, float xr, float xh,
                                      float hz, float hr, float hh, float h) {
  float z = 1.f / (1.f + expf(-(xz + hz)));
  float r = 1.f / (1.f + expf(-(xr + hr)));
  float c = tanhf(xh + r * hh);
  return z * h + (1.f - z) * c;
}

__global__ void k_h_init(const int* __restrict__ nodes, const float* __restrict__ embed) {
  int idx = blockIdx.x * blockDim.x + threadIdx.x;
  if (idx >= NN * HD) return;
  int v = idx >> 8, j = idx & 255;
  int tok = __ldg(&nodes[v]);
  int pos = __ldg(&nodes[NN + v]);
  int p = pos < 512 ? pos : 512;
  float pe = 0.f;
  if (p > 0) {
    float ang = (float)(p - 1) * exp2f(-(float)j * 0.10381025296523f);
    pe = (j & 1) ? cosf(ang) : sinf(ang);
  }
  g_h[idx] = __ldg(&embed[(size_t)tok * HD + j]) + pe;
}

__global__ void k_zero_deg() {
  int i = blockIdx.x * blockDim.x + threadIdx.x;
  if (i < NN) g_deg[i] = 0;
}

__global__ void k_init_misc(const int* __restrict__ sizes, float* __restrict__ out) {
  int t = threadIdx.x;
  if (t < NG) g_sums[t] = 0.f;
  if (t < 2 * NG) out[t] = 0.f;
  if (t == 0) {
    g_gmax = 0u;
    int s = 0;
    for (int i = 0; i < NG; i++) { s += sizes[i]; g_cum[i] = s; }
  }
}

__global__ void k_count(const int* __restrict__ edges) {
  int i = blockIdx.x * blockDim.x + threadIdx.x;
  if (i < NE) atomicAdd(&g_deg[edges[3 * i + 2]], 1);
}

__global__ void k_scan() {
  __shared__ int sCarry;
  __shared__ int warpTot[32];
  int tid = threadIdx.x;
  int lane = tid & 31, wid = tid >> 5;
  if (tid == 0) sCarry = 0;
  __syncthreads();
  for (int base = 0; base < NN; base += 1024) {
    int i = base + tid;
    int v = (i < NN) ? g_deg[i] : 0;
    int x = v;
#pragma unroll
    for (int off = 1; off < 32; off <<= 1) {
      int y = __shfl_up_sync(~0u, x, off);
      if (lane >= off) x += y;
    }
    if (lane == 31) warpTot[wid] = x;
    __syncthreads();
    if (wid == 0) {
      int w = warpTot[lane];
#pragma unroll
      for (int off = 1; off < 32; off <<= 1) {
        int y = __shfl_up_sync(~0u, w, off);
        if (lane >= off) w += y;
      }
      warpTot[lane] = w;
    }
    __syncthreads();
    int warpPrefix = (wid > 0) ? warpTot[wid - 1] : 0;
    int incl = x + warpPrefix;
    int excl = incl - v;
    int carry = sCarry;
    if (i < NN) { g_rowoff[i] = carry + excl; g_cursor[i] = carry + excl; }
    __syncthreads();
    if (tid == 1023) sCarry = carry + incl;
    __syncthreads();
  }
  if (tid == 0) g_rowoff[NN] = sCarry;
}

__global__ void k_fill(const int* __restrict__ edges) {
  int i = blockIdx.x * blockDim.x + threadIdx.x;
  if (i >= NE) return;
  int et = edges[3 * i], src = edges[3 * i + 1], tgt = edges[3 * i + 2];
  int p = atomicAdd(&g_cursor[tgt], 1);
  g_csr[p] = (src << 2) | et;
}

// C[M, gridY*128] = A[M,256] @ B (+bias).  Column block n0 selects weight block
// tB = n0/nblk, local col nb0 = n0%nblk.
__global__ __launch_bounds__(256)
void k_gemm(const float* __restrict__ A, int M,
            const float* __restrict__ B, int ldb, int nblk, long nblkStride,
            const float* __restrict__ bias, int biasBlkStride,
            float* __restrict__ C, int ldc) {
  __shared__ __align__(16) float As[128][36];
  __shared__ __align__(16) float Bs[32][136];
  int m0 = blockIdx.x * 128;
  int n0 = blockIdx.y * 128;
  int tB = n0 / nblk;
  int nb0 = n0 % nblk;
  const float* Bblk = B + (size_t)tB * nblkStride + nb0;
  int tid = threadIdx.x;
  int lane = tid & 31, warp = tid >> 5;
  int wm = (warp & 3) * 32;
  int wn = (warp >> 2) * 64;

  float acc[2][8][4];
#pragma unroll
  for (int i = 0; i < 2; i++)
#pragma unroll
    for (int j = 0; j < 8; j++)
#pragma unroll
      for (int k = 0; k < 4; k++) acc[i][j][k] = 0.f;

  for (int k0 = 0; k0 < HD; k0 += 32) {
#pragma unroll
    for (int p = 0; p < 4; p++) {
      int r = p * 32 + (tid >> 3);
      int c = (tid & 7) * 4;
      float4 v = make_float4(0.f, 0.f, 0.f, 0.f);
      if (m0 + r < M) v = *(const float4*)(A + (size_t)(m0 + r) * HD + k0 + c);
      v.x = to_tf32(v.x); v.y = to_tf32(v.y); v.z = to_tf32(v.z); v.w = to_tf32(v.w);
      *(float4*)&As[r][c] = v;
    }
#pragma unroll
    for (int p = 0; p < 4; p++) {
      int r = p * 8 + (tid >> 5);
      int c = (tid & 31) * 4;
      float4 v = *(const float4*)(Bblk + (size_t)(k0 + r) * ldb + c);
      v.x = to_tf32(v.x); v.y = to_tf32(v.y); v.z = to_tf32(v.z); v.w = to_tf32(v.w);
      *(float4*)&Bs[r][c] = v;
    }
    __syncthreads();
#pragma unroll
    for (int ks = 0; ks < 4; ks++) {
      int kk = ks * 8;
      unsigned af[2][4], bf[8][2];
#pragma unroll
      for (int mt = 0; mt < 2; mt++) {
        int r = wm + mt * 16 + (lane >> 2);
        int cA = kk + (lane & 3);
        af[mt][0] = __float_as_uint(As[r][cA]);
        af[mt][1] = __float_as_uint(As[r + 8][cA]);
        af[mt][2] = __float_as_uint(As[r][cA + 4]);
        af[mt][3] = __float_as_uint(As[r + 8][cA + 4]);
      }
#pragma unroll
      for (int nt = 0; nt < 8; nt++) {
        int cN = wn + nt * 8 + (lane >> 2);
        int rB = kk + (lane & 3);
        bf[nt][0] = __float_as_uint(Bs[rB][cN]);
        bf[nt][1] = __float_as_uint(Bs[rB + 4][cN]);
      }
#pragma unroll
      for (int mt = 0; mt < 2; mt++)
#pragma unroll
        for (int nt = 0; nt < 8; nt++) mma_tf32(acc[mt][nt], af[mt], bf[nt]);
    }
    __syncthreads();
  }

#pragma unroll
  for (int mt = 0; mt < 2; mt++) {
    int r0 = m0 + wm + mt * 16 + (lane >> 2);
#pragma unroll
    for (int nt = 0; nt < 8; nt++) {
      int cc = wn + nt * 8 + 2 * (lane & 3);
      float b0 = __ldg(&bias[(size_t)tB * biasBlkStride + nb0 + cc]);
      float b1 = __ldg(&bias[(size_t)tB * biasBlkStride + nb0 + cc + 1]);
      int gn = n0 + cc;
      if (r0 < M) {
        C[(size_t)r0 * ldc + gn] = acc[mt][nt][0] + b0;
        C[(size_t)r0 * ldc + gn + 1] = acc[mt][nt][1] + b1;
      }
      if (r0 + 8 < M) {
        C[(size_t)(r0 + 8) * ldc + gn] = acc[mt][nt][2] + b0;
        C[(size_t)(r0 + 8) * ldc + gn + 1] = acc[mt][nt][3] + b1;
      }
    }
  }
}

__global__ void k_msgs() {
  int gw = (blockIdx.x * blockDim.x + threadIdx.x) >> 5;
  int lane = threadIdx.x & 31;
  if (gw >= NN) return;
  int beg = g_rowoff[gw], end = g_rowoff[gw + 1];
  float4 a0 = make_float4(0.f, 0.f, 0.f, 0.f);
  float4 a1 = make_float4(0.f, 0.f, 0.f, 0.f);
  for (int i = beg; i < end; i++) {
    int e = g_csr[i];
    const float4* p = (const float4*)(g_trans +
        ((size_t)(e >> 2) * (NT * HD) + (size_t)(e & 3) * HD));
    float4 x0 = p[lane], x1 = p[lane + 32];
    a0.x += x0.x; a0.y += x0.y; a0.z += x0.z; a0.w += x0.w;
    a1.x += x1.x; a1.y += x1.y; a1.z += x1.z; a1.w += x1.w;
  }
  float4* o = (float4*)(g_msgs + (size_t)gw * HD);
  o[lane] = a0;
  o[lane + 32] = a1;
}

__global__ void k_gru() {
  int idx = blockIdx.x * blockDim.x + threadIdx.x;
  if (idx >= NN * 64) return;
  int v = idx >> 6, q = idx & 63;
  const float4* px = (const float4*)(g_gx + (size_t)v * 768);
  const float4* ph = (const float4*)(g_gh + (size_t)v * 768);
  float4 xz = px[q], xr = px[q + 64], xh = px[q + 128];
  float4 hz = ph[q], hr = ph[q + 64], hh = ph[q + 128];
  float4 hv = ((const float4*)g_h)[idx];
  float4 r;
  r.x = gru1(xz.x, xr.x, xh.x, hz.x, hr.x, hh.x, hv.x);
  r.y = gru1(xz.y, xr.y, xh.y, hz.y, hr.y, hh.y, hv.y);
  r.z = gru1(xz.z, xr.z, xh.z, hz.z, hr.z, hh.z, hv.z);
  r.w = gru1(xz.w, xr.w, xh.w, hz.w, hr.w, hh.w, hv.w);
  ((float4*)g_h)[idx] = r;
}

__global__ void k_readout1(const float* __restrict__ gateW, const float* __restrict__ gateB,
                           const float* __restrict__ outW, const float* __restrict__ outB) {
  int warp = threadIdx.x >> 5, lane = threadIdx.x & 31;
  int v = blockIdx.x * 8 + warp;
  float g = 0.f, o0 = 0.f, o1 = 0.f;
  if (v < NN) {
    const float* hv = g_h + (size_t)v * HD;
#pragma unroll 4
    for (int j = lane; j < HD; j += 32) {
      float x = hv[j];
      g += x * __ldg(&gateW[j]);
      float2 w = __ldg((const float2*)outW + j);
      o0 += x * w.x;
      o1 += x * w.y;
    }
  }
#pragma unroll
  for (int off = 16; off; off >>= 1) {
    g += __shfl_xor_sync(~0u, g, off);
    o0 += __shfl_xor_sync(~0u, o0, off);
    o1 += __shfl_xor_sync(~0u, o1, off);
  }
  float gl = g + __ldg(gateB);
  if (v < NN && lane == 0) {
    g_gate[v] = gl;
    g_outs[2 * v] = o0 + __ldg(&outB[0]);
    g_outs[2 * v + 1] = o1 + __ldg(&outB[1]);
  }
  __shared__ float smax[8];
  if (lane == 0) smax[warp] = (v < NN) ? gl : -3.4e38f;
  __syncthreads();
  if (threadIdx.x == 0) {
    float m = smax[0];
#pragma unroll
    for (int i = 1; i < 8; i++) m = fmaxf(m, smax[i]);
    atomicMax(&g_gmax, fenc(m));
  }
}

__global__ void k_readout2() {
  int v = blockIdx.x * blockDim.x + threadIdx.x;
  __shared__ float part[4];
  __shared__ int s0;
  if (threadIdx.x < 4) part[threadIdx.x] = 0.f;
  if (threadIdx.x == 0) s0 = find_seg(blockIdx.x * blockDim.x);
  __syncthreads();
  if (v < NN) {
    float e = expf(g_gate[v] - fdec(g_gmax));
    g_gate[v] = e;
    int s = find_seg(v);
    atomicAdd(&part[s - s0], e);
  }
  __syncthreads();
  if (threadIdx.x < 4 && part[threadIdx.x] != 0.f)
    atomicAdd(&g_sums[s0 + threadIdx.x], part[threadIdx.x]);
}

__global__ void k_readout3(float* __restrict__ out) {
  int v = blockIdx.x * blockDim.x + threadIdx.x;
  __shared__ float p0[4], p1[4];
  __shared__ int s0;
  if (threadIdx.x < 4) { p0[threadIdx.x] = 0.f; p1[threadIdx.x] = 0.f; }
  if (threadIdx.x == 0) s0 = find_seg(blockIdx.x * blockDim.x);
  __syncthreads();
  if (v < NN) {
    int s = find_seg(v);
    float w = g_gate[v] / (g_sums[s] + 1e-16f);
    atomicAdd(&p0[s - s0], g_outs[2 * v] * w);
    atomicAdd(&p1[s - s0], g_outs[2 * v + 1] * w);
  }
  __syncthreads();
  if (threadIdx.x < 4) {
    int s = s0 + threadIdx.x;
    if (s < NG && (p0[threadIdx.x] != 0.f || p1[threadIdx.x] != 0.f)) {
      atomicAdd(&out[2 * s], p0[threadIdx.x]);
      atomicAdd(&out[2 * s + 1], p1[threadIdx.x]);
    }
  }
}

extern "C" void kernel_launch(void* const* d_in, const int* in_sizes, int n_in,
                              void* d_out, int out_size) {
  const int* nodes = (const int*)d_in[0];
  const int* gsizes = (const int*)d_in[1];
  const int* edges = (const int*)d_in[2];
  const float* embed = (const float*)d_in[3];
  const float* tw = (const float*)d_in[4];   // [2,4,256,256]
  const float* tb = (const float*)d_in[5];   // [2,4,256]
  const float* gW = (const float*)d_in[6];   // [2,256,768]
  const float* gU = (const float*)d_in[7];   // [2,256,768]
  const float* gbi = (const float*)d_in[8];  // [2,768]
  const float* gbr = (const float*)d_in[9];  // [2,768]
  const float* gateW = (const float*)d_in[10];
  const float* gateB = (const float*)d_in[11];
  const float* outW = (const float*)d_in[12];
  const float* outB = (const float*)d_in[13];
  float* out = (float*)d_out;

  k_h_init<<<(NN * HD + 255) / 256, 256>>>(nodes, embed);
  k_zero_deg<<<(NN + 255) / 256, 256>>>();
  k_init_misc<<<1, 256>>>(gsizes, out);
  k_count<<<(NE + 255) / 256, 256>>>(edges);
  k_scan<<<1, 1024>>>();
  k_fill<<<(NE + 255) / 256, 256>>>(edges);

  float* hptr;  cudaGetSymbolAddress((void**)&hptr, g_h);
  float* trptr; cudaGetSymbolAddress((void**)&trptr, g_trans);
  float* msptr; cudaGetSymbolAddress((void**)&msptr, g_msgs);
  float* gxptr; cudaGetSymbolAddress((void**)&gxptr, g_gx);
  float* ghptr; cudaGetSymbolAddress((void**)&ghptr, g_gh);

  const int steps[2] = {3, 1};
  dim3 gT((NN + 127) / 128, 8);
  dim3 gG((NN + 127) / 128, 6);
  for (int l = 0; l < 2; l++) {
    const float* Wt = tw + (size_t)l * NT * HD * HD;
    const float* bt = tb + (size_t)l * NT * HD;
    const float* Wx = gW + (size_t)l * HD * 768;
    const float* Uh = gU + (size_t)l * HD * 768;
    const float* bi = gbi + (size_t)l * 768;
    const float* br = gbr + (size_t)l * 768;
    for (int s = 0; s < steps[l]; s++) {
      k_gemm<<<gT, 256>>>(hptr, NN, Wt, HD, HD, (long)HD * HD, bt, HD, trptr, NT * HD);
      k_msgs<<<(NN * 32 + 255) / 256, 256>>>();
      k_gemm<<<gG, 256>>>(msptr, NN, Wx, 768, 768, 0, bi, 0, gxptr, 768);
      k_gemm<<<gG, 256>>>(hptr, NN, Uh, 768, 768, 0, br, 0, ghptr, 768);
      k_gru<<<(NN * 64 + 255) / 256, 256>>>();
    }
  }
  k_readout1<<<(NN + 7) / 8, 256>>>(gateW, gateB, outW, outB);
  k_readout2<<<(NN + 255) / 256, 256>>>();
  k_readout3<<<(NN + 255) / 256, 256>>>(out);
}

// round 3
// speedup vs baseline: 1.0486x; 1.0486x over previous
#include <cuda_runtime.h>
#include <cstdint>
#include <math.h>

#define NN 100000
#define NG 100
#define NE 1000000
#define HD 256
#define NT 4

#define ASTRIDE 36
#define BSTRIDE 136
#define ASTG (128 * ASTRIDE)
#define BSTG (32 * BSTRIDE)
#define GEMM_SMEM ((2 * ASTG + 2 * BSTG) * 4)

__device__ float g_h[(size_t)NN * HD];      // exact state
__device__ float g_htf[(size_t)NN * HD];    // tf32-rounded copy of h
__device__ float g_trans[(size_t)NN * NT * HD];
__device__ float g_msgs[(size_t)NN * HD];   // tf32-rounded at store
__device__ float g_gx[(size_t)NN * 3 * HD];
__device__ float g_gh[(size_t)NN * 3 * HD];
__device__ float g_twr[2 * NT * HD * HD];   // rounded weights
__device__ float g_gWr[2 * HD * 3 * HD];
__device__ float g_gUr[2 * HD * 3 * HD];
__device__ float g_gate[NN];
__device__ float g_outs[2 * NN];
__device__ float g_sums[NG];
__device__ unsigned g_gmax;
__device__ int g_deg[NN];
__device__ int g_rowoff[NN + 1];
__device__ int g_cursor[NN];
__device__ int g_csr[NE];
__device__ int g_cum[NG];

__device__ __forceinline__ float to_tf32(float x) {
  unsigned u;
  asm("cvt.rna.tf32.f32 %0, %1;" : "=r"(u) : "f"(x));
  return __uint_as_float(u);
}
__device__ __forceinline__ void mma_tf32(float* d, const unsigned* a, const unsigned* b) {
  asm volatile(
      "mma.sync.aligned.m16n8k8.row.col.f32.tf32.tf32.f32 "
      "{%0,%1,%2,%3}, {%4,%5,%6,%7}, {%8,%9}, {%0,%1,%2,%3};\n"
      : "+f"(d[0]), "+f"(d[1]), "+f"(d[2]), "+f"(d[3])
      : "r"(a[0]), "r"(a[1]), "r"(a[2]), "r"(a[3]), "r"(b[0]), "r"(b[1]));
}
__device__ __forceinline__ void cpa16(float* dst, const float* src, bool pred) {
  unsigned d = (unsigned)__cvta_generic_to_shared(dst);
  int sz = pred ? 16 : 0;
  asm volatile("cp.async.cg.shared.global [%0], [%1], 16, %2;\n" :: "r"(d), "l"(src), "r"(sz));
}
__device__ __forceinline__ unsigned fenc(float f) {
  unsigned u = __float_as_uint(f);
  return (u & 0x80000000u) ? ~u : (u | 0x80000000u);
}
__device__ __forceinline__ float fdec(unsigned e) {
  return (e & 0x80000000u) ? __uint_as_float(e & 0x7fffffffu) : __uint_as_float(~e);
}
__device__ __forceinline__ int find_seg(int v) {
  int lo = 0, hi = NG;
  while (lo < hi) { int mid = (lo + hi) >> 1; if (g_cum[mid] > v) hi = mid; else lo = mid + 1; }
  return lo;
}
__device__ __forceinline__ float gru1(float xz, float xr, float xh,
                                      float hz, float hr, float hh, float h) {
  float z = 1.f / (1.f + expf(-(xz + hz)));
  float r = 1.f / (1.f + expf(-(xr + hr)));
  float c = tanhf(xh + r * hh);
  return z * h + (1.f - z) * c;
}

__global__ void k_h_init(const int* __restrict__ nodes, const float* __restrict__ embed) {
  int idx = blockIdx.x * blockDim.x + threadIdx.x;
  if (idx >= NN * HD) return;
  int v = idx >> 8, j = idx & 255;
  int tok = __ldg(&nodes[v]);
  int pos = __ldg(&nodes[NN + v]);
  int p = pos < 512 ? pos : 512;
  float pe = 0.f;
  if (p > 0) {
    float ang = (float)(p - 1) * exp2f(-(float)j * 0.10381025296523f);
    pe = (j & 1) ? cosf(ang) : sinf(ang);
  }
  float h = __ldg(&embed[(size_t)tok * HD + j]) + pe;
  g_h[idx] = h;
  g_htf[idx] = to_tf32(h);
}

__global__ void k_round_w(const float* __restrict__ tw, const float* __restrict__ gW,
                          const float* __restrict__ gU) {
  int i = blockIdx.x * blockDim.x + threadIdx.x;
  if (i < 2 * NT * HD * HD) g_twr[i] = to_tf32(__ldg(&tw[i]));
  if (i < 2 * HD * 3 * HD) {
    g_gWr[i] = to_tf32(__ldg(&gW[i]));
    g_gUr[i] = to_tf32(__ldg(&gU[i]));
  }
}

__global__ void k_zero_deg() {
  int i = blockIdx.x * blockDim.x + threadIdx.x;
  if (i < NN) g_deg[i] = 0;
}

__global__ void k_init_misc(const int* __restrict__ sizes, float* __restrict__ out) {
  int t = threadIdx.x;
  if (t < NG) g_sums[t] = 0.f;
  if (t < 2 * NG) out[t] = 0.f;
  if (t == 0) {
    g_gmax = 0u;
    int s = 0;
    for (int i = 0; i < NG; i++) { s += sizes[i]; g_cum[i] = s; }
  }
}

__global__ void k_count(const int* __restrict__ edges) {
  int i = blockIdx.x * blockDim.x + threadIdx.x;
  if (i < NE) atomicAdd(&g_deg[edges[3 * i + 2]], 1);
}

__global__ void k_scan() {
  __shared__ int sCarry;
  __shared__ int warpTot[32];
  int tid = threadIdx.x;
  int lane = tid & 31, wid = tid >> 5;
  if (tid == 0) sCarry = 0;
  __syncthreads();
  for (int base = 0; base < NN; base += 1024) {
    int i = base + tid;
    int v = (i < NN) ? g_deg[i] : 0;
    int x = v;
#pragma unroll
    for (int off = 1; off < 32; off <<= 1) {
      int y = __shfl_up_sync(~0u, x, off);
      if (lane >= off) x += y;
    }
    if (lane == 31) warpTot[wid] = x;
    __syncthreads();
    if (wid == 0) {
      int w = warpTot[lane];
#pragma unroll
      for (int off = 1; off < 32; off <<= 1) {
        int y = __shfl_up_sync(~0u, w, off);
        if (lane >= off) w += y;
      }
      warpTot[lane] = w;
    }
    __syncthreads();
    int warpPrefix = (wid > 0) ? warpTot[wid - 1] : 0;
    int incl = x + warpPrefix;
    int excl = incl - v;
    int carry = sCarry;
    if (i < NN) { g_rowoff[i] = carry + excl; g_cursor[i] = carry + excl; }
    __syncthreads();
    if (tid == 1023) sCarry = carry + incl;
    __syncthreads();
  }
  if (tid == 0) g_rowoff[NN] = sCarry;
}

__global__ void k_fill(const int* __restrict__ edges) {
  int i = blockIdx.x * blockDim.x + threadIdx.x;
  if (i >= NE) return;
  int et = edges[3 * i], src = edges[3 * i + 1], tgt = edges[3 * i + 2];
  int p = atomicAdd(&g_cursor[tgt], 1);
  g_csr[p] = (src << 2) | et;
}

// C[M, gridY*128] = A[M,256] @ B (+bias); inputs pre-rounded to tf32.
// 2-stage cp.async pipeline, BK=32.
__global__ __launch_bounds__(256)
void k_gemm(const float* __restrict__ A, int M,
            const float* __restrict__ B, int ldb, int nblk, long nblkStride,
            const float* __restrict__ bias, int biasBlkStride,
            float* __restrict__ C, int ldc) {
  extern __shared__ float sm[];
  float* As = sm;               // [2][128][36]
  float* Bs = sm + 2 * ASTG;    // [2][32][136]
  int m0 = blockIdx.x * 128;
  int n0 = blockIdx.y * 128;
  int tB = n0 / nblk;
  int nb0 = n0 - tB * nblk;
  const float* Bblk = B + (size_t)tB * nblkStride + nb0;
  int tid = threadIdx.x, lane = tid & 31, warp = tid >> 5;
  int wm = (warp & 3) * 32, wn = (warp >> 2) * 64;
  int ar = tid >> 3, ac = (tid & 7) * 4;
  int br = tid >> 5, bc = (tid & 31) * 4;
  size_t arow[4];
  bool apred[4];
#pragma unroll
  for (int p = 0; p < 4; p++) {
    int r = m0 + ar + p * 32;
    apred[p] = r < M;
    arow[p] = apred[p] ? (size_t)r : 0;
  }

  float acc[2][8][4];
#pragma unroll
  for (int i = 0; i < 2; i++)
#pragma unroll
    for (int j = 0; j < 8; j++)
#pragma unroll
      for (int k = 0; k < 4; k++) acc[i][j][k] = 0.f;

  // prologue: stage 0
#pragma unroll
  for (int p = 0; p < 4; p++)
    cpa16(&As[(ar + p * 32) * ASTRIDE + ac], A + arow[p] * HD + ac, apred[p]);
#pragma unroll
  for (int p = 0; p < 4; p++)
    cpa16(&Bs[(br + p * 8) * BSTRIDE + bc], Bblk + (size_t)(br + p * 8) * ldb + bc, true);
  asm volatile("cp.async.commit_group;\n");

#pragma unroll
  for (int kt = 0; kt < 8; kt++) {
    int s = kt & 1;
    if (kt < 7) {
      int s2 = (kt + 1) & 1;
      int k0 = (kt + 1) * 32;
#pragma unroll
      for (int p = 0; p < 4; p++)
        cpa16(&As[s2 * ASTG + (ar + p * 32) * ASTRIDE + ac], A + arow[p] * HD + k0 + ac, apred[p]);
#pragma unroll
      for (int p = 0; p < 4; p++)
        cpa16(&Bs[s2 * BSTG + (br + p * 8) * BSTRIDE + bc],
              Bblk + (size_t)(k0 + br + p * 8) * ldb + bc, true);
      asm volatile("cp.async.commit_group;\n");
      asm volatile("cp.async.wait_group 1;\n");
    } else {
      asm volatile("cp.async.wait_group 0;\n");
    }
    __syncthreads();
    const float* Asb = As + s * ASTG;
    const float* Bsb = Bs + s * BSTG;
#pragma unroll
    for (int ks = 0; ks < 4; ks++) {
      int kk = ks * 8;
      unsigned af[2][4], bf[8][2];
#pragma unroll
      for (int mt = 0; mt < 2; mt++) {
        int r = wm + mt * 16 + (lane >> 2);
        int cA = kk + (lane & 3);
        af[mt][0] = __float_as_uint(Asb[r * ASTRIDE + cA]);
        af[mt][1] = __float_as_uint(Asb[(r + 8) * ASTRIDE + cA]);
        af[mt][2] = __float_as_uint(Asb[r * ASTRIDE + cA + 4]);
        af[mt][3] = __float_as_uint(Asb[(r + 8) * ASTRIDE + cA + 4]);
      }
#pragma unroll
      for (int nt = 0; nt < 8; nt++) {
        int cN = wn + nt * 8 + (lane >> 2);
        int rB = kk + (lane & 3);
        bf[nt][0] = __float_as_uint(Bsb[rB * BSTRIDE + cN]);
        bf[nt][1] = __float_as_uint(Bsb[(rB + 4) * BSTRIDE + cN]);
      }
#pragma unroll
      for (int mt = 0; mt < 2; mt++)
#pragma unroll
        for (int nt = 0; nt < 8; nt++) mma_tf32(acc[mt][nt], af[mt], bf[nt]);
    }
    __syncthreads();
  }

#pragma unroll
  for (int mt = 0; mt < 2; mt++) {
    int r0 = m0 + wm + mt * 16 + (lane >> 2);
#pragma unroll
    for (int nt = 0; nt < 8; nt++) {
      int cc = wn + nt * 8 + 2 * (lane & 3);
      float b0 = __ldg(&bias[(size_t)tB * biasBlkStride + nb0 + cc]);
      float b1 = __ldg(&bias[(size_t)tB * biasBlkStride + nb0 + cc + 1]);
      int gn = n0 + cc;
      if (r0 < M) {
        C[(size_t)r0 * ldc + gn] = acc[mt][nt][0] + b0;
        C[(size_t)r0 * ldc + gn + 1] = acc[mt][nt][1] + b1;
      }
      if (r0 + 8 < M) {
        C[(size_t)(r0 + 8) * ldc + gn] = acc[mt][nt][2] + b0;
        C[(size_t)(r0 + 8) * ldc + gn + 1] = acc[mt][nt][3] + b1;
      }
    }
  }
}

__global__ void k_msgs() {
  int gw = (blockIdx.x * blockDim.x + threadIdx.x) >> 5;
  int lane = threadIdx.x & 31;
  if (gw >= NN) return;
  int beg = g_rowoff[gw], end = g_rowoff[gw + 1];
  float4 a0 = make_float4(0.f, 0.f, 0.f, 0.f);
  float4 a1 = make_float4(0.f, 0.f, 0.f, 0.f);
  int i = beg;
  for (; i + 1 < end; i += 2) {
    int e0 = g_csr[i], e1 = g_csr[i + 1];
    const float4* p0 = (const float4*)(g_trans +
        ((size_t)(e0 >> 2) * (NT * HD) + (size_t)(e0 & 3) * HD));
    const float4* p1 = (const float4*)(g_trans +
        ((size_t)(e1 >> 2) * (NT * HD) + (size_t)(e1 & 3) * HD));
    float4 x0 = p0[lane], x1 = p0[lane + 32];
    float4 y0 = p1[lane], y1 = p1[lane + 32];
    a0.x += x0.x + y0.x; a0.y += x0.y + y0.y; a0.z += x0.z + y0.z; a0.w += x0.w + y0.w;
    a1.x += x1.x + y1.x; a1.y += x1.y + y1.y; a1.z += x1.z + y1.z; a1.w += x1.w + y1.w;
  }
  if (i < end) {
    int e0 = g_csr[i];
    const float4* p0 = (const float4*)(g_trans +
        ((size_t)(e0 >> 2) * (NT * HD) + (size_t)(e0 & 3) * HD));
    float4 x0 = p0[lane], x1 = p0[lane + 32];
    a0.x += x0.x; a0.y += x0.y; a0.z += x0.z; a0.w += x0.w;
    a1.x += x1.x; a1.y += x1.y; a1.z += x1.z; a1.w += x1.w;
  }
  a0.x = to_tf32(a0.x); a0.y = to_tf32(a0.y); a0.z = to_tf32(a0.z); a0.w = to_tf32(a0.w);
  a1.x = to_tf32(a1.x); a1.y = to_tf32(a1.y); a1.z = to_tf32(a1.z); a1.w = to_tf32(a1.w);
  float4* o = (float4*)(g_msgs + (size_t)gw * HD);
  o[lane] = a0;
  o[lane + 32] = a1;
}

__global__ void k_gru() {
  int idx = blockIdx.x * blockDim.x + threadIdx.x;
  if (idx >= NN * 64) return;
  int v = idx >> 6, q = idx & 63;
  const float4* px = (const float4*)(g_gx + (size_t)v * 768);
  const float4* ph = (const float4*)(g_gh + (size_t)v * 768);
  float4 xz = px[q], xr = px[q + 64], xh = px[q + 128];
  float4 hz = ph[q], hr = ph[q + 64], hh = ph[q + 128];
  float4 hv = ((const float4*)g_h)[idx];
  float4 r;
  r.x = gru1(xz.x, xr.x, xh.x, hz.x, hr.x, hh.x, hv.x);
  r.y = gru1(xz.y, xr.y, xh.y, hz.y, hr.y, hh.y, hv.y);
  r.z = gru1(xz.z, xr.z, xh.z, hz.z, hr.z, hh.z, hv.z);
  r.w = gru1(xz.w, xr.w, xh.w, hz.w, hr.w, hh.w, hv.w);
  ((float4*)g_h)[idx] = r;
  float4 t;
  t.x = to_tf32(r.x); t.y = to_tf32(r.y); t.z = to_tf32(r.z); t.w = to_tf32(r.w);
  ((float4*)g_htf)[idx] = t;
}

__global__ void k_readout1(const float* __restrict__ gateW, const float* __restrict__ gateB,
                           const float* __restrict__ outW, const float* __restrict__ outB) {
  int warp = threadIdx.x >> 5, lane = threadIdx.x & 31;
  int v = blockIdx.x * 8 + warp;
  float g = 0.f, o0 = 0.f, o1 = 0.f;
  if (v < NN) {
    const float* hv = g_h + (size_t)v * HD;
#pragma unroll 4
    for (int j = lane; j < HD; j += 32) {
      float x = hv[j];
      g += x * __ldg(&gateW[j]);
      float2 w = __ldg((const float2*)outW + j);
      o0 += x * w.x;
      o1 += x * w.y;
    }
  }
#pragma unroll
  for (int off = 16; off; off >>= 1) {
    g += __shfl_xor_sync(~0u, g, off);
    o0 += __shfl_xor_sync(~0u, o0, off);
    o1 += __shfl_xor_sync(~0u, o1, off);
  }
  float gl = g + __ldg(gateB);
  if (v < NN && lane == 0) {
    g_gate[v] = gl;
    g_outs[2 * v] = o0 + __ldg(&outB[0]);
    g_outs[2 * v + 1] = o1 + __ldg(&outB[1]);
  }
  __shared__ float smax[8];
  if (lane == 0) smax[warp] = (v < NN) ? gl : -3.4e38f;
  __syncthreads();
  if (threadIdx.x == 0) {
    float m = smax[0];
#pragma unroll
    for (int i = 1; i < 8; i++) m = fmaxf(m, smax[i]);
    atomicMax(&g_gmax, fenc(m));
  }
}

__global__ void k_readout2() {
  int v = blockIdx.x * blockDim.x + threadIdx.x;
  __shared__ float part[4];
  __shared__ int s0;
  if (threadIdx.x < 4) part[threadIdx.x] = 0.f;
  if (threadIdx.x == 0) s0 = find_seg(blockIdx.x * blockDim.x);
  __syncthreads();
  if (v < NN) {
    float e = expf(g_gate[v] - fdec(g_gmax));
    g_gate[v] = e;
    int s = find_seg(v);
    atomicAdd(&part[s - s0], e);
  }
  __syncthreads();
  if (threadIdx.x < 4 && part[threadIdx.x] != 0.f)
    atomicAdd(&g_sums[s0 + threadIdx.x], part[threadIdx.x]);
}

__global__ void k_readout3(float* __restrict__ out) {
  int v = blockIdx.x * blockDim.x + threadIdx.x;
  __shared__ float p0[4], p1[4];
  __shared__ int s0;
  if (threadIdx.x < 4) { p0[threadIdx.x] = 0.f; p1[threadIdx.x] = 0.f; }
  if (threadIdx.x == 0) s0 = find_seg(blockIdx.x * blockDim.x);
  __syncthreads();
  if (v < NN) {
    int s = find_seg(v);
    float w = g_gate[v] / (g_sums[s] + 1e-16f);
    atomicAdd(&p0[s - s0], g_outs[2 * v] * w);
    atomicAdd(&p1[s - s0], g_outs[2 * v + 1] * w);
  }
  __syncthreads();
  if (threadIdx.x < 4) {
    int s = s0 + threadIdx.x;
    if (s < NG && (p0[threadIdx.x] != 0.f || p1[threadIdx.x] != 0.f)) {
      atomicAdd(&out[2 * s], p0[threadIdx.x]);
      atomicAdd(&out[2 * s + 1], p1[threadIdx.x]);
    }
  }
}

extern "C" void kernel_launch(void* const* d_in, const int* in_sizes, int n_in,
                              void* d_out, int out_size) {
  const int* nodes = (const int*)d_in[0];
  const int* gsizes = (const int*)d_in[1];
  const int* edges = (const int*)d_in[2];
  const float* embed = (const float*)d_in[3];
  const float* tw = (const float*)d_in[4];   // [2,4,256,256]
  const float* tb = (const float*)d_in[5];   // [2,4,256]
  const float* gW = (const float*)d_in[6];   // [2,256,768]
  const float* gU = (const float*)d_in[7];   // [2,256,768]
  const float* gbi = (const float*)d_in[8];  // [2,768]
  const float* gbr = (const float*)d_in[9];  // [2,768]
  const float* gateW = (const float*)d_in[10];
  const float* gateB = (const float*)d_in[11];
  const float* outW = (const float*)d_in[12];
  const float* outB = (const float*)d_in[13];
  float* out = (float*)d_out;

  cudaFuncSetAttribute(k_gemm, cudaFuncAttributeMaxDynamicSharedMemorySize, GEMM_SMEM);

  k_h_init<<<(NN * HD + 255) / 256, 256>>>(nodes, embed);
  k_round_w<<<(2 * NT * HD * HD + 255) / 256, 256>>>(tw, gW, gU);
  k_zero_deg<<<(NN + 255) / 256, 256>>>();
  k_init_misc<<<1, 256>>>(gsizes, out);
  k_count<<<(NE + 255) / 256, 256>>>(edges);
  k_scan<<<1, 1024>>>();
  k_fill<<<(NE + 255) / 256, 256>>>(edges);

  float* htf;   cudaGetSymbolAddress((void**)&htf, g_htf);
  float* trptr; cudaGetSymbolAddress((void**)&trptr, g_trans);
  float* msptr; cudaGetSymbolAddress((void**)&msptr, g_msgs);
  float* gxptr; cudaGetSymbolAddress((void**)&gxptr, g_gx);
  float* ghptr; cudaGetSymbolAddress((void**)&ghptr, g_gh);
  float* twr;   cudaGetSymbolAddress((void**)&twr, g_twr);
  float* gWr;   cudaGetSymbolAddress((void**)&gWr, g_gWr);
  float* gUr;   cudaGetSymbolAddress((void**)&gUr, g_gUr);

  const int steps[2] = {3, 1};
  dim3 gT((NN + 127) / 128, 8);
  dim3 gG((NN + 127) / 128, 6);
  for (int l = 0; l < 2; l++) {
    const float* Wt = twr + (size_t)l * NT * HD * HD;
    const float* bt = tb + (size_t)l * NT * HD;
    const float* Wx = gWr + (size_t)l * HD * 768;
    const float* Uh = gUr + (size_t)l * HD * 768;
    const float* bi = gbi + (size_t)l * 768;
    const float* br = gbr + (size_t)l * 768;
    for (int s = 0; s < steps[l]; s++) {
      k_gemm<<<gT, 256, GEMM_SMEM>>>(htf, NN, Wt, HD, HD, (long)HD * HD, bt, HD, trptr, NT * HD);
      k_msgs<<<(NN * 32 + 255) / 256, 256>>>();
      k_gemm<<<gG, 256, GEMM_SMEM>>>(msptr, NN, Wx, 768, 768, 0, bi, 0, gxptr, 768);
      k_gemm<<<gG, 256, GEMM_SMEM>>>(htf, NN, Uh, 768, 768, 0, br, 0, ghptr, 768);
      k_gru<<<(NN * 64 + 255) / 256, 256>>>();
    }
  }
  k_readout1<<<(NN + 7) / 8, 256>>>(gateW, gateB, outW, outB);
  k_readout2<<<(NN + 255) / 256, 256>>>();
  k_readout3<<<(NN + 255) / 256, 256>>>(out);
}